// round 14
// baseline (speedup 1.0000x reference)
#include <cuda_runtime.h>
#include <math.h>

#define B_   32
#define C_   1280
#define HW_  1024
#define TD_  768
#define LD_  64
#define EPSV 1e-5f
#define LORA_SCALE_V 0.125f   // 64^-0.5
#define FLT_MAX_V 3.402823466e+38f
#define FB   160               // blocks in fused front kernel

// ---------------- scratch (device globals; no allocs allowed) ----------------
__device__ __align__(128) float g_q[C_];
__device__ __align__(128) float g_lq[LD_];
__device__ __align__(128) float g_w[C_];
__device__ __align__(128) float g_cst[32];
__device__ __align__(128) float g_sim[B_ * HW_];
__device__ __align__(128) float g_mu[B_ * HW_];
__device__ __align__(128) float g_rs[B_ * HW_];
__device__ __align__(128) unsigned g_barcnt;   // monotonic; never reset (replay-safe)

// ---------------- reduction helpers ----------------
__device__ __forceinline__ float warpSum(float v) {
#pragma unroll
    for (int o = 16; o > 0; o >>= 1) v += __shfl_xor_sync(0xffffffffu, v, o);
    return v;
}
__device__ __forceinline__ float warpMax(float v) {
#pragma unroll
    for (int o = 16; o > 0; o >>= 1) v = fmaxf(v, __shfl_xor_sync(0xffffffffu, v, o));
    return v;
}
__device__ float blockSum(float v, float* sm) {
    int lane = threadIdx.x & 31, w = threadIdx.x >> 5;
    int nw = (blockDim.x + 31) >> 5;
    v = warpSum(v);
    if (lane == 0) sm[w] = v;
    __syncthreads();
    if (w == 0) {
        float x = (lane < nw) ? sm[lane] : 0.f;
        x = warpSum(x);
        if (lane == 0) sm[32] = x;
    }
    __syncthreads();
    float r = sm[32];
    __syncthreads();
    return r;
}
__device__ float blockMax(float v, float* sm) {
    int lane = threadIdx.x & 31, w = threadIdx.x >> 5;
    int nw = (blockDim.x + 31) >> 5;
    v = warpMax(v);
    if (lane == 0) sm[w] = v;
    __syncthreads();
    if (w == 0) {
        float x = (lane < nw) ? sm[lane] : -FLT_MAX_V;
        x = warpMax(x);
        if (lane == 0) sm[32] = x;
    }
    __syncthreads();
    float r = sm[32];
    __syncthreads();
    return r;
}

// Grid barrier for exactly FB co-resident blocks (proven R8).
__device__ __forceinline__ void gridBar() {
    __syncthreads();
    if (threadIdx.x == 0) {
        __threadfence();
        unsigned v = atomicAdd(&g_barcnt, 1u);
        unsigned gen = v / FB;
        while ((*(volatile unsigned*)&g_barcnt) / FB == gen) { }
    }
    __syncthreads();
}

// ---------------- K1 (fused front): q -> lora_q -> w_eff -> constants ----------
__global__ void __launch_bounds__(256) k_front(const float* __restrict__ emb,
                                               const float* __restrict__ qg,
                                               const float* __restrict__ qb,
                                               const float* __restrict__ toqw,
                                               const float* __restrict__ lqw,
                                               const float* __restrict__ lkw,
                                               const float* __restrict__ lng,
                                               const float* __restrict__ lnb) {
    __shared__ __align__(16) float t[TD_];
    __shared__ float sm[33];
    __shared__ float sc[8 * 9];
    int tid = threadIdx.x, lane = tid & 31, w = tid >> 5;

    // ---- Phase A: token LN (redundant per block, L2) + q projection ----
    {
        float s = 0.f, s2 = 0.f;
#pragma unroll
        for (int i = 0; i < 3; i++) { float v = emb[tid + 256 * i]; s += v; s2 += v * v; }
        s = blockSum(s, sm);
        s2 = blockSum(s2, sm);
        float mu = s / (float)TD_;
        float var = s2 / (float)TD_ - mu * mu;
        float r = rsqrtf(var + EPSV);
#pragma unroll
        for (int i = 0; i < 3; i++) {
            int idx = tid + 256 * i;
            t[idx] = (emb[idx] - mu) * r * qg[idx] + qb[idx];
        }
        __syncthreads();
        int c = blockIdx.x * 8 + w;
        const float4* row4 = (const float4*)(toqw + (size_t)c * TD_);
        const float4* t4 = (const float4*)t;
        float acc = 0.f;
#pragma unroll
        for (int j = 0; j < 6; j++) {
            float4 a = row4[lane + 32 * j];
            float4 x = t4[lane + 32 * j];
            acc += a.x * x.x + a.y * x.y + a.z * x.z + a.w * x.w;
        }
        acc = warpSum(acc);
        if (lane == 0) g_q[c] = acc;
    }
    gridBar();

    // ---- Phase B: lora_q (blocks 0..7, warp per d, LN folded) ----
    if (blockIdx.x < 8) {
        float s = 0.f, s2 = 0.f;
#pragma unroll
        for (int i = 0; i < 5; i++) { float v = g_q[tid + 256 * i]; s += v; s2 += v * v; }
        s = blockSum(s, sm);
        s2 = blockSum(s2, sm);
        float mu = s / (float)C_;
        float var = s2 / (float)C_ - mu * mu;
        float r = rsqrtf(var + EPSV);
        int d = blockIdx.x * 8 + w;
        const float4* row4 = (const float4*)(lqw + (size_t)d * C_);
        const float4* q4 = (const float4*)g_q;
        float a = 0.f, sr = 0.f;
#pragma unroll
        for (int j = 0; j < 10; j++) {
            float4 rr = row4[lane + 32 * j];
            float4 qq = q4[lane + 32 * j];
            a += rr.x * qq.x + rr.y * qq.y + rr.z * qq.z + rr.w * qq.w;
            sr += rr.x + rr.y + rr.z + rr.w;
        }
        a = warpSum(a);
        sr = warpSum(sr);
        if (lane == 0) g_lq[d] = (a - mu * sr) * r;
    }
    gridBar();

    // ---- Phase C: w_eff (all blocks, warp per c, lanes over d) ----
    {
        int c = blockIdx.x * 8 + w;
        float lq0 = g_lq[lane], lq1 = g_lq[lane + 32];
        float pv = lq0 * lkw[(size_t)lane * C_ + c]
                 + lq1 * lkw[(size_t)(lane + 32) * C_ + c];
        pv = warpSum(pv);
        if (lane == 0) g_w[c] = pv;
    }
    gridBar();

    // ---- Phase D: constants (block 0 only) ----
    if (blockIdx.x != 0) return;
    {
        float p[9];
#pragma unroll
        for (int j = 0; j < 9; j++) p[j] = 0.f;
#pragma unroll
        for (int cc = 0; cc < 5; cc++) {
            int c = tid + 256 * cc;
            float wv = g_w[c];
            float g = lng[c], b = lnb[c];
            p[0] += g; p[1] += g * g; p[2] += g * b; p[3] += b; p[4] += b * b;
            p[5] += g * wv; p[6] += b * wv; p[7] += wv;
            p[8] += fabsf(g - 1.f) + fabsf(b);
        }
#pragma unroll
        for (int j = 0; j < 9; j++) {
            p[j] = warpSum(p[j]);
            if (lane == 0) sc[w * 9 + j] = p[j];
        }
        __syncthreads();
        if (tid < 9) {
            float r = 0.f;
#pragma unroll
            for (int ww = 0; ww < 8; ww++) r += sc[ww * 9 + tid];
            g_cst[tid] = r;
        }
    }
}

// ---------------- K2: sim per row — skips masked rows; streaming loads ----------
__global__ void __launch_bounds__(256) k_sim(const float* __restrict__ kin,
                                             const float* __restrict__ lng,
                                             const float* __restrict__ lnb,
                                             const float* __restrict__ mask) {
    int row = blockIdx.x * 8 + (threadIdx.x >> 5);   // b*HW+s
    int lane = threadIdx.x & 31;
    if (mask[row] <= 0.f) return;   // masked -> softmax forces -inf; skip 5KB read
    const float4* z4 = (const float4*)(kin + (size_t)row * C_);
    const float4* w4 = (const float4*)g_w;
    bool triv = (g_cst[8] < 1e-6f);
    float S1 = 0.f, S2 = 0.f, S3 = 0.f, S4 = 0.f, S5 = 0.f, S6 = 0.f, S7 = 0.f;
    if (triv) {
#pragma unroll
        for (int j = 0; j < 10; j++) {
            float4 z = __ldcs(&z4[lane + 32 * j]);   // read-once: evict-first
            float4 w = w4[lane + 32 * j];
            S1 += z.x + z.y + z.z + z.w;
            S2 += z.x * z.x + z.y * z.y + z.z * z.z + z.w * z.w;
            S7 += z.x * w.x + z.y * w.y + z.z * w.z + z.w * w.w;
        }
        S3 = S1; S4 = S1; S5 = S2; S6 = 0.f;
    } else {
        const float4* gg4 = (const float4*)lng;
        const float4* bb4 = (const float4*)lnb;
#pragma unroll
        for (int j = 0; j < 10; j++) {
            float4 z = __ldcs(&z4[lane + 32 * j]);
            float4 g = gg4[lane + 32 * j];
            float4 b = bb4[lane + 32 * j];
            float4 w = w4[lane + 32 * j];
            float gz0 = z.x * g.x, gz1 = z.y * g.y, gz2 = z.z * g.z, gz3 = z.w * g.w;
            S1 += z.x + z.y + z.z + z.w;
            S2 += z.x * z.x + z.y * z.y + z.z * z.z + z.w * z.w;
            S3 += gz0 + gz1 + gz2 + gz3;
            S4 += g.x * gz0 + g.y * gz1 + g.z * gz2 + g.w * gz3;
            S5 += gz0 * gz0 + gz1 * gz1 + gz2 * gz2 + gz3 * gz3;
            S6 += b.x * gz0 + b.y * gz1 + b.z * gz2 + b.w * gz3;
            S7 += w.x * gz0 + w.y * gz1 + w.z * gz2 + w.w * gz3;
        }
    }
    S1 = warpSum(S1); S2 = warpSum(S2); S3 = warpSum(S3); S4 = warpSum(S4);
    S5 = warpSum(S5); S6 = warpSum(S6); S7 = warpSum(S7);
    if (lane == 0) {
        const float Cf = (float)C_;
        float Sg = g_cst[0], Sg2 = g_cst[1], Sgb = g_cst[2], Sb = g_cst[3];
        float Sb2 = g_cst[4], Sgw = g_cst[5], Sbw = g_cst[6], Sw = g_cst[7];
        float mu = S1 / Cf;
        float var = S2 / Cf - mu * mu;
        float r = rsqrtf(var + EPSV);
        float sk  = r * (S3 - mu * Sg) + Sb;
        float mu2 = sk / Cf;
        float sk2 = r * r * (S5 - 2.f * mu * S4 + mu * mu * Sg2)
                  + 2.f * r * (S6 - mu * Sgb) + Sb2;
        float var2 = sk2 / Cf - mu2 * mu2;
        float r2 = rsqrtf(var2 + EPSV);
        float skw = r * (S7 - mu * Sgw) + Sbw;
        g_sim[row] = LORA_SCALE_V * r2 * (skw - mu2 * Sw);
    }
}

// ---------------- K3: per-s LN stats of x (forked; streaming loads) -------------
__global__ void __launch_bounds__(256) k_xstats(const float* __restrict__ infeat) {
    int b = blockIdx.x >> 4;
    int s0 = (blockIdx.x & 15) * 64;
    int sl = threadIdx.x & 63;
    int cg = threadIdx.x >> 6;    // 0..3
    const float* base = infeat + (size_t)b * C_ * HW_ + s0 + sl;
    float s = 0.f, s2 = 0.f;
#pragma unroll 16
    for (int c = cg; c < C_; c += 4) {
        float v = __ldcs(&base[(size_t)c * HW_]);
        s += v; s2 += v * v;
    }
    __shared__ float sh[2][4][64];
    sh[0][cg][sl] = s; sh[1][cg][sl] = s2;
    __syncthreads();
    if (cg == 0) {
        s  = sh[0][0][sl] + sh[0][1][sl] + sh[0][2][sl] + sh[0][3][sl];
        s2 = sh[1][0][sl] + sh[1][1][sl] + sh[1][2][sl] + sh[1][3][sl];
        float mu = s / (float)C_;
        float var = s2 / (float)C_ - mu * mu;
        int idx = b * HW_ + s0 + sl;
        g_mu[idx] = mu;
        g_rs[idx] = rsqrtf(var + EPSV);
    }
}

// ---------------- K4: fused softmax + fg/bg weighted sums (32 c per block) ------
// Double-buffered half-row batches; outputs emitted per row (low live state);
// launch_bounds(256,4): target 4 blocks/SM -> ~32 warps, ~64KB in flight.
__global__ void __launch_bounds__(256, 4) k_out(const float* __restrict__ infeat,
                                                const float* __restrict__ lng,
                                                const float* __restrict__ lnb,
                                                const float* __restrict__ mask,
                                                float* __restrict__ out) {
    __shared__ __align__(16) float wA[HW_];
    __shared__ __align__(16) float wB[HW_];
    __shared__ float sm[33];
    int tid = threadIdx.x, lane = tid & 31, w = tid >> 5;
    int b = blockIdx.x / 40;
    int cg = blockIdx.x - b * 40;      // 0..39, 32 c each

    // ---- per-batch softmax (redundant across the 40 blocks of this batch) ----
    {
        float loc[4];
        float mx = -FLT_MAX_V;
#pragma unroll
        for (int i = 0; i < 4; i++) {
            int s = tid + 256 * i;
            float m = mask[b * HW_ + s];
            float sv = (m > 0.f) ? g_sim[b * HW_ + s] : -FLT_MAX_V;
            loc[i] = sv;
            mx = fmaxf(mx, sv);
        }
        mx = blockMax(mx, sm);
        float es = 0.f;
#pragma unroll
        for (int i = 0; i < 4; i++) {
            float e = __expf(loc[i] - mx);
            loc[i] = e; es += e;
        }
        es = blockSum(es, sm);
        float inv = 1.f / es;
        float pA = 0.f, p2 = 0.f;
        const float invHW = 1.f / (float)HW_;
#pragma unroll
        for (int i = 0; i < 4; i++) {
            int s = tid + 256 * i;
            int idx = b * HW_ + s;
            float attn = loc[i] * inv;
            float rs = g_rs[idx], mu = g_mu[idx];
            float a = attn * rs;
            wA[s] = a;
            wB[s] = rs * invHW - a;
            pA += attn * mu * rs;
            p2 += mu * rs * invHW;
        }
        float cA = blockSum(pA, sm);
        float cB = blockSum(p2, sm) - cA;
        if (tid == 0) { sm[0] = cA; sm[1] = cB; }
    }
    __syncthreads();
    float cA = sm[0], cB = sm[1];

    // ---- body: warp w covers 4 rows c0..c0+3, double-buffered half-rows ----
    int c0 = cg * 32 + w * 4;
    const float4* a4 = (const float4*)wA;
    const float4* w4 = (const float4*)wB;
    const float4* xp = (const float4*)(infeat + (size_t)(b * C_ + c0) * HW_);
    // row stride in float4 units = HW_/4 = 256
    float4 buf0[4], buf1[4];
#pragma unroll
    for (int j = 0; j < 4; j++) buf0[j] = __ldcs(&xp[lane + 32 * j]);   // row0 1st half
#pragma unroll
    for (int r = 0; r < 4; r++) {
        const float4* xr = xp + r * 256;
#pragma unroll
        for (int j = 0; j < 4; j++) buf1[j] = __ldcs(&xr[lane + 32 * (j + 4)]); // 2nd half
        float sf = 0.f, sb = 0.f;
#pragma unroll
        for (int j = 0; j < 4; j++) {
            float4 wa = a4[lane + 32 * j];
            float4 wb = w4[lane + 32 * j];
            sf += buf0[j].x * wa.x + buf0[j].y * wa.y + buf0[j].z * wa.z + buf0[j].w * wa.w;
            sb += buf0[j].x * wb.x + buf0[j].y * wb.y + buf0[j].z * wb.z + buf0[j].w * wb.w;
        }
        if (r < 3) {
            const float4* xn = xp + (r + 1) * 256;
#pragma unroll
            for (int j = 0; j < 4; j++) buf0[j] = __ldcs(&xn[lane + 32 * j]);   // next row 1st half
        }
#pragma unroll
        for (int j = 0; j < 4; j++) {
            float4 wa = a4[lane + 32 * (j + 4)];
            float4 wb = w4[lane + 32 * (j + 4)];
            sf += buf1[j].x * wa.x + buf1[j].y * wa.y + buf1[j].z * wa.z + buf1[j].w * wa.w;
            sb += buf1[j].x * wb.x + buf1[j].y * wb.y + buf1[j].z * wb.z + buf1[j].w * wb.w;
        }
        sf = warpSum(sf);
        sb = warpSum(sb);
        if (lane == 0) {
            int c = c0 + r;
            float g = lng[c], bb = lnb[c];
            out[b * (2 * C_) + c]       = g * (sf - cA) + bb;
            out[b * (2 * C_) + C_ + c]  = g * (sb - cB);
        }
    }
}

// ---------------- launch (4 kernels, fork preserved) ----------------
extern "C" void kernel_launch(void* const* d_in, const int* in_sizes, int n_in,
                              void* d_out, int out_size) {
    const float* layer_infeat  = (const float*)d_in[0];
    const float* layer_inquery = (const float*)d_in[1];
    const float* token_q_emb   = (const float*)d_in[2];
    const float* to_q_w        = (const float*)d_in[3];
    const float* ln_x_g        = (const float*)d_in[4];
    const float* ln_x_b        = (const float*)d_in[5];
    const float* ln_k_g        = (const float*)d_in[6];
    const float* ln_k_b        = (const float*)d_in[7];
    const float* ln_q_g        = (const float*)d_in[8];
    const float* ln_q_b        = (const float*)d_in[9];
    const float* lora_q_w      = (const float*)d_in[10];
    const float* lora_k_w      = (const float*)d_in[11];
    const float* mask          = (const float*)d_in[12];
    float* out = (float*)d_out;

    cudaStream_t s1;
    cudaStreamCreateWithFlags(&s1, cudaStreamNonBlocking);
    cudaEvent_t evF, evB;
    cudaEventCreateWithFlags(&evF, cudaEventDisableTiming);
    cudaEventCreateWithFlags(&evB, cudaEventDisableTiming);

    // Fork: stream B streams ALL of infeat (160MB) while the default stream
    // runs the fused front kernel + the masked inquery pass.
    cudaEventRecord(evF, 0);
    cudaStreamWaitEvent(s1, evF, 0);
    k_xstats<<<512, 256, 0, s1>>>(layer_infeat);
    cudaEventRecord(evB, s1);

    k_front<<<FB, 256>>>(token_q_emb, ln_q_g, ln_q_b, to_q_w,
                         lora_q_w, lora_k_w, ln_k_g, ln_k_b);
    k_sim<<<4096, 256>>>(layer_inquery, ln_k_g, ln_k_b, mask);

    // Join: k_out needs g_sim (default) and g_mu/g_rs (stream B).
    cudaStreamWaitEvent(0, evB, 0);
    k_out<<<B_ * 40, 256>>>(layer_infeat, ln_x_g, ln_x_b, mask, out);
}

// round 15
// speedup vs baseline: 1.2084x; 1.2084x over previous
#include <cuda_runtime.h>
#include <math.h>

#define B_   32
#define C_   1280
#define HW_  1024
#define TD_  768
#define LD_  64
#define EPSV 1e-5f
#define LORA_SCALE_V 0.125f   // 64^-0.5
#define FLT_MAX_V 3.402823466e+38f
#define FB   160               // blocks in fused front kernel

// ---------------- scratch (device globals; no allocs allowed) ----------------
__device__ __align__(128) float g_q[C_];
__device__ __align__(128) float g_lq[LD_];
__device__ __align__(128) float g_w[C_];
__device__ __align__(128) float g_cst[32];
__device__ __align__(128) float g_sim[B_ * HW_];
__device__ __align__(128) float g_mu[B_ * HW_];
__device__ __align__(128) float g_rs[B_ * HW_];
__device__ __align__(128) unsigned g_barcnt;   // monotonic; never reset (replay-safe)

// ---------------- reduction helpers ----------------
__device__ __forceinline__ float warpSum(float v) {
#pragma unroll
    for (int o = 16; o > 0; o >>= 1) v += __shfl_xor_sync(0xffffffffu, v, o);
    return v;
}
__device__ __forceinline__ float warpMax(float v) {
#pragma unroll
    for (int o = 16; o > 0; o >>= 1) v = fmaxf(v, __shfl_xor_sync(0xffffffffu, v, o));
    return v;
}
__device__ float blockSum(float v, float* sm) {
    int lane = threadIdx.x & 31, w = threadIdx.x >> 5;
    int nw = (blockDim.x + 31) >> 5;
    v = warpSum(v);
    if (lane == 0) sm[w] = v;
    __syncthreads();
    if (w == 0) {
        float x = (lane < nw) ? sm[lane] : 0.f;
        x = warpSum(x);
        if (lane == 0) sm[32] = x;
    }
    __syncthreads();
    float r = sm[32];
    __syncthreads();
    return r;
}
__device__ float blockMax(float v, float* sm) {
    int lane = threadIdx.x & 31, w = threadIdx.x >> 5;
    int nw = (blockDim.x + 31) >> 5;
    v = warpMax(v);
    if (lane == 0) sm[w] = v;
    __syncthreads();
    if (w == 0) {
        float x = (lane < nw) ? sm[lane] : -FLT_MAX_V;
        x = warpMax(x);
        if (lane == 0) sm[32] = x;
    }
    __syncthreads();
    float r = sm[32];
    __syncthreads();
    return r;
}

// Grid barrier for exactly FB co-resident blocks (proven R8).
__device__ __forceinline__ void gridBar() {
    __syncthreads();
    if (threadIdx.x == 0) {
        __threadfence();
        unsigned v = atomicAdd(&g_barcnt, 1u);
        unsigned gen = v / FB;
        while ((*(volatile unsigned*)&g_barcnt) / FB == gen) { }
    }
    __syncthreads();
}

// ---------------- K1 (fused front): q -> lora_q -> w_eff -> constants ----------
__global__ void __launch_bounds__(256) k_front(const float* __restrict__ emb,
                                               const float* __restrict__ qg,
                                               const float* __restrict__ qb,
                                               const float* __restrict__ toqw,
                                               const float* __restrict__ lqw,
                                               const float* __restrict__ lkw,
                                               const float* __restrict__ lng,
                                               const float* __restrict__ lnb) {
    __shared__ __align__(16) float t[TD_];
    __shared__ float sm[33];
    __shared__ float sc[8 * 9];
    int tid = threadIdx.x, lane = tid & 31, w = tid >> 5;

    // ---- Phase A: token LN (redundant per block, L2) + q projection ----
    {
        float s = 0.f, s2 = 0.f;
#pragma unroll
        for (int i = 0; i < 3; i++) { float v = emb[tid + 256 * i]; s += v; s2 += v * v; }
        s = blockSum(s, sm);
        s2 = blockSum(s2, sm);
        float mu = s / (float)TD_;
        float var = s2 / (float)TD_ - mu * mu;
        float r = rsqrtf(var + EPSV);
#pragma unroll
        for (int i = 0; i < 3; i++) {
            int idx = tid + 256 * i;
            t[idx] = (emb[idx] - mu) * r * qg[idx] + qb[idx];
        }
        __syncthreads();
        int c = blockIdx.x * 8 + w;
        const float4* row4 = (const float4*)(toqw + (size_t)c * TD_);
        const float4* t4 = (const float4*)t;
        float acc = 0.f;
#pragma unroll
        for (int j = 0; j < 6; j++) {
            float4 a = row4[lane + 32 * j];
            float4 x = t4[lane + 32 * j];
            acc += a.x * x.x + a.y * x.y + a.z * x.z + a.w * x.w;
        }
        acc = warpSum(acc);
        if (lane == 0) g_q[c] = acc;
    }
    gridBar();

    // ---- Phase B: lora_q (blocks 0..7, warp per d, LN folded) ----
    if (blockIdx.x < 8) {
        float s = 0.f, s2 = 0.f;
#pragma unroll
        for (int i = 0; i < 5; i++) { float v = g_q[tid + 256 * i]; s += v; s2 += v * v; }
        s = blockSum(s, sm);
        s2 = blockSum(s2, sm);
        float mu = s / (float)C_;
        float var = s2 / (float)C_ - mu * mu;
        float r = rsqrtf(var + EPSV);
        int d = blockIdx.x * 8 + w;
        const float4* row4 = (const float4*)(lqw + (size_t)d * C_);
        const float4* q4 = (const float4*)g_q;
        float a = 0.f, sr = 0.f;
#pragma unroll
        for (int j = 0; j < 10; j++) {
            float4 rr = row4[lane + 32 * j];
            float4 qq = q4[lane + 32 * j];
            a += rr.x * qq.x + rr.y * qq.y + rr.z * qq.z + rr.w * qq.w;
            sr += rr.x + rr.y + rr.z + rr.w;
        }
        a = warpSum(a);
        sr = warpSum(sr);
        if (lane == 0) g_lq[d] = (a - mu * sr) * r;
    }
    gridBar();

    // ---- Phase C: w_eff (all blocks, warp per c, lanes over d) ----
    {
        int c = blockIdx.x * 8 + w;
        float lq0 = g_lq[lane], lq1 = g_lq[lane + 32];
        float pv = lq0 * lkw[(size_t)lane * C_ + c]
                 + lq1 * lkw[(size_t)(lane + 32) * C_ + c];
        pv = warpSum(pv);
        if (lane == 0) g_w[c] = pv;
    }
    gridBar();

    // ---- Phase D: constants (block 0 only) ----
    if (blockIdx.x != 0) return;
    {
        float p[9];
#pragma unroll
        for (int j = 0; j < 9; j++) p[j] = 0.f;
#pragma unroll
        for (int cc = 0; cc < 5; cc++) {
            int c = tid + 256 * cc;
            float wv = g_w[c];
            float g = lng[c], b = lnb[c];
            p[0] += g; p[1] += g * g; p[2] += g * b; p[3] += b; p[4] += b * b;
            p[5] += g * wv; p[6] += b * wv; p[7] += wv;
            p[8] += fabsf(g - 1.f) + fabsf(b);
        }
#pragma unroll
        for (int j = 0; j < 9; j++) {
            p[j] = warpSum(p[j]);
            if (lane == 0) sc[w * 9 + j] = p[j];
        }
        __syncthreads();
        if (tid < 9) {
            float r = 0.f;
#pragma unroll
            for (int ww = 0; ww < 8; ww++) r += sc[ww * 9 + tid];
            g_cst[tid] = r;
        }
    }
}

// ---------------- K2: sim per row — skips masked rows (NO cache hints) ----------
__global__ void __launch_bounds__(256) k_sim(const float* __restrict__ kin,
                                             const float* __restrict__ lng,
                                             const float* __restrict__ lnb,
                                             const float* __restrict__ mask) {
    int row = blockIdx.x * 8 + (threadIdx.x >> 5);   // b*HW+s
    int lane = threadIdx.x & 31;
    if (mask[row] <= 0.f) return;   // masked -> softmax forces -inf; skip 5KB read
    const float4* z4 = (const float4*)(kin + (size_t)row * C_);
    const float4* w4 = (const float4*)g_w;
    bool triv = (g_cst[8] < 1e-6f);
    float S1 = 0.f, S2 = 0.f, S3 = 0.f, S4 = 0.f, S5 = 0.f, S6 = 0.f, S7 = 0.f;
    if (triv) {
#pragma unroll
        for (int j = 0; j < 10; j++) {
            float4 z = z4[lane + 32 * j];
            float4 w = w4[lane + 32 * j];
            S1 += z.x + z.y + z.z + z.w;
            S2 += z.x * z.x + z.y * z.y + z.z * z.z + z.w * z.w;
            S7 += z.x * w.x + z.y * w.y + z.z * w.z + z.w * w.w;
        }
        S3 = S1; S4 = S1; S5 = S2; S6 = 0.f;
    } else {
        const float4* gg4 = (const float4*)lng;
        const float4* bb4 = (const float4*)lnb;
#pragma unroll
        for (int j = 0; j < 10; j++) {
            float4 z = z4[lane + 32 * j];
            float4 g = gg4[lane + 32 * j];
            float4 b = bb4[lane + 32 * j];
            float4 w = w4[lane + 32 * j];
            float gz0 = z.x * g.x, gz1 = z.y * g.y, gz2 = z.z * g.z, gz3 = z.w * g.w;
            S1 += z.x + z.y + z.z + z.w;
            S2 += z.x * z.x + z.y * z.y + z.z * z.z + z.w * z.w;
            S3 += gz0 + gz1 + gz2 + gz3;
            S4 += g.x * gz0 + g.y * gz1 + g.z * gz2 + g.w * gz3;
            S5 += gz0 * gz0 + gz1 * gz1 + gz2 * gz2 + gz3 * gz3;
            S6 += b.x * gz0 + b.y * gz1 + b.z * gz2 + b.w * gz3;
            S7 += w.x * gz0 + w.y * gz1 + w.z * gz2 + w.w * gz3;
        }
    }
    S1 = warpSum(S1); S2 = warpSum(S2); S3 = warpSum(S3); S4 = warpSum(S4);
    S5 = warpSum(S5); S6 = warpSum(S6); S7 = warpSum(S7);
    if (lane == 0) {
        const float Cf = (float)C_;
        float Sg = g_cst[0], Sg2 = g_cst[1], Sgb = g_cst[2], Sb = g_cst[3];
        float Sb2 = g_cst[4], Sgw = g_cst[5], Sbw = g_cst[6], Sw = g_cst[7];
        float mu = S1 / Cf;
        float var = S2 / Cf - mu * mu;
        float r = rsqrtf(var + EPSV);
        float sk  = r * (S3 - mu * Sg) + Sb;
        float mu2 = sk / Cf;
        float sk2 = r * r * (S5 - 2.f * mu * S4 + mu * mu * Sg2)
                  + 2.f * r * (S6 - mu * Sgb) + Sb2;
        float var2 = sk2 / Cf - mu2 * mu2;
        float r2 = rsqrtf(var2 + EPSV);
        float skw = r * (S7 - mu * Sgw) + Sbw;
        g_sim[row] = LORA_SCALE_V * r2 * (skw - mu2 * Sw);
    }
}

// ---------------- K3: per-s LN stats of x (forked; NO cache hints) --------------
__global__ void __launch_bounds__(256) k_xstats(const float* __restrict__ infeat) {
    int b = blockIdx.x >> 4;
    int s0 = (blockIdx.x & 15) * 64;
    int sl = threadIdx.x & 63;
    int cg = threadIdx.x >> 6;    // 0..3
    const float* base = infeat + (size_t)b * C_ * HW_ + s0 + sl;
    float s = 0.f, s2 = 0.f;
#pragma unroll 16
    for (int c = cg; c < C_; c += 4) {
        float v = base[(size_t)c * HW_];
        s += v; s2 += v * v;
    }
    __shared__ float sh[2][4][64];
    sh[0][cg][sl] = s; sh[1][cg][sl] = s2;
    __syncthreads();
    if (cg == 0) {
        s  = sh[0][0][sl] + sh[0][1][sl] + sh[0][2][sl] + sh[0][3][sl];
        s2 = sh[1][0][sl] + sh[1][1][sl] + sh[1][2][sl] + sh[1][3][sl];
        float mu = s / (float)C_;
        float var = s2 / (float)C_ - mu * mu;
        int idx = b * HW_ + s0 + sl;
        g_mu[idx] = mu;
        g_rs[idx] = rsqrtf(var + EPSV);
    }
}

// ---------------- K4: fused softmax + fg/bg weighted sums (64 c per block) ------
// 20 blocks per batch (grid 640): preamble instances halved vs R13 and waves
// drop to ~1.4 at 3 blocks/SM. Warp covers 8 c rows; double-buffered half-row
// batches keep ~2KB per warp in flight; per-row immediate reduce keeps regs low.
__global__ void __launch_bounds__(256, 3) k_out(const float* __restrict__ infeat,
                                                const float* __restrict__ lng,
                                                const float* __restrict__ lnb,
                                                const float* __restrict__ mask,
                                                float* __restrict__ out) {
    __shared__ __align__(16) float wA[HW_];
    __shared__ __align__(16) float wB[HW_];
    __shared__ float sm[33];
    int tid = threadIdx.x, lane = tid & 31, w = tid >> 5;
    int b = blockIdx.x / 20;
    int cg = blockIdx.x - b * 20;      // 0..19, 64 c each

    // ---- per-batch softmax (redundant across the 20 blocks of this batch) ----
    {
        float loc[4];
        float mx = -FLT_MAX_V;
#pragma unroll
        for (int i = 0; i < 4; i++) {
            int s = tid + 256 * i;
            float m = mask[b * HW_ + s];
            float sv = (m > 0.f) ? g_sim[b * HW_ + s] : -FLT_MAX_V;
            loc[i] = sv;
            mx = fmaxf(mx, sv);
        }
        mx = blockMax(mx, sm);
        float es = 0.f;
#pragma unroll
        for (int i = 0; i < 4; i++) {
            float e = __expf(loc[i] - mx);
            loc[i] = e; es += e;
        }
        es = blockSum(es, sm);
        float inv = 1.f / es;
        float pA = 0.f, p2 = 0.f;
        const float invHW = 1.f / (float)HW_;
#pragma unroll
        for (int i = 0; i < 4; i++) {
            int s = tid + 256 * i;
            int idx = b * HW_ + s;
            float attn = loc[i] * inv;
            float rs = g_rs[idx], mu = g_mu[idx];
            float a = attn * rs;
            wA[s] = a;
            wB[s] = rs * invHW - a;
            pA += attn * mu * rs;
            p2 += mu * rs * invHW;
        }
        float cA = blockSum(pA, sm);
        float cB = blockSum(p2, sm) - cA;
        if (tid == 0) { sm[0] = cA; sm[1] = cB; }
    }
    __syncthreads();
    float cA = sm[0], cB = sm[1];

    // ---- body: warp w covers 8 rows c0..c0+7, double-buffered half-rows ----
    int c0 = cg * 64 + w * 8;
    const float4* a4 = (const float4*)wA;
    const float4* w4 = (const float4*)wB;
    const float4* xp = (const float4*)(infeat + (size_t)(b * C_ + c0) * HW_);
    // row stride in float4 units = HW_/4 = 256
    float4 buf0[4], buf1[4];
#pragma unroll
    for (int j = 0; j < 4; j++) buf0[j] = xp[lane + 32 * j];      // row0 1st half
#pragma unroll
    for (int r = 0; r < 8; r++) {
        const float4* xr = xp + r * 256;
#pragma unroll
        for (int j = 0; j < 4; j++) buf1[j] = xr[lane + 32 * (j + 4)];  // 2nd half
        float sf = 0.f, sb = 0.f;
#pragma unroll
        for (int j = 0; j < 4; j++) {
            float4 wa = a4[lane + 32 * j];
            float4 wb = w4[lane + 32 * j];
            sf += buf0[j].x * wa.x + buf0[j].y * wa.y + buf0[j].z * wa.z + buf0[j].w * wa.w;
            sb += buf0[j].x * wb.x + buf0[j].y * wb.y + buf0[j].z * wb.z + buf0[j].w * wb.w;
        }
        if (r < 7) {
            const float4* xn = xp + (r + 1) * 256;
#pragma unroll
            for (int j = 0; j < 4; j++) buf0[j] = xn[lane + 32 * j];    // next row 1st half
        }
#pragma unroll
        for (int j = 0; j < 4; j++) {
            float4 wa = a4[lane + 32 * (j + 4)];
            float4 wb = w4[lane + 32 * (j + 4)];
            sf += buf1[j].x * wa.x + buf1[j].y * wa.y + buf1[j].z * wa.z + buf1[j].w * wa.w;
            sb += buf1[j].x * wb.x + buf1[j].y * wb.y + buf1[j].z * wb.z + buf1[j].w * wb.w;
        }
        sf = warpSum(sf);
        sb = warpSum(sb);
        if (lane == 0) {
            int c = c0 + r;
            float g = lng[c], bb = lnb[c];
            out[b * (2 * C_) + c]       = g * (sf - cA) + bb;
            out[b * (2 * C_) + C_ + c]  = g * (sb - cB);
        }
    }
}

// ---------------- launch (4 kernels, fork preserved) ----------------
extern "C" void kernel_launch(void* const* d_in, const int* in_sizes, int n_in,
                              void* d_out, int out_size) {
    const float* layer_infeat  = (const float*)d_in[0];
    const float* layer_inquery = (const float*)d_in[1];
    const float* token_q_emb   = (const float*)d_in[2];
    const float* to_q_w        = (const float*)d_in[3];
    const float* ln_x_g        = (const float*)d_in[4];
    const float* ln_x_b        = (const float*)d_in[5];
    const float* ln_k_g        = (const float*)d_in[6];
    const float* ln_k_b        = (const float*)d_in[7];
    const float* ln_q_g        = (const float*)d_in[8];
    const float* ln_q_b        = (const float*)d_in[9];
    const float* lora_q_w      = (const float*)d_in[10];
    const float* lora_k_w      = (const float*)d_in[11];
    const float* mask          = (const float*)d_in[12];
    float* out = (float*)d_out;

    cudaStream_t s1;
    cudaStreamCreateWithFlags(&s1, cudaStreamNonBlocking);
    cudaEvent_t evF, evB;
    cudaEventCreateWithFlags(&evF, cudaEventDisableTiming);
    cudaEventCreateWithFlags(&evB, cudaEventDisableTiming);

    // Fork: stream B streams ALL of infeat (160MB) while the default stream
    // runs the fused front kernel + the masked inquery pass.
    cudaEventRecord(evF, 0);
    cudaStreamWaitEvent(s1, evF, 0);
    k_xstats<<<512, 256, 0, s1>>>(layer_infeat);
    cudaEventRecord(evB, s1);

    k_front<<<FB, 256>>>(token_q_emb, ln_q_g, ln_q_b, to_q_w,
                         lora_q_w, lora_k_w, ln_k_g, ln_k_b);
    k_sim<<<4096, 256>>>(layer_inquery, ln_k_g, ln_k_b, mask);

    // Join: k_out needs g_sim (default) and g_mu/g_rs (stream B).
    cudaStreamWaitEvent(0, evB, 0);
    k_out<<<B_ * 20, 256>>>(layer_infeat, ln_x_g, ln_x_b, mask, out);
}

// round 17
// speedup vs baseline: 1.6429x; 1.3595x over previous
#include <cuda_runtime.h>
#include <math.h>

#define B_   32
#define C_   1280
#define HW_  1024
#define TD_  768
#define LD_  64
#define EPSV 1e-5f
#define LORA_SCALE_V 0.125f   // 64^-0.5
#define FLT_MAX_V 3.402823466e+38f
#define FB   160               // blocks in fused front kernel

// ---------------- scratch (device globals; no allocs allowed) ----------------
__device__ __align__(128) float g_q[C_];
__device__ __align__(128) float g_lq[LD_];
__device__ __align__(128) float g_w[C_];
__device__ __align__(128) float g_cst[32];
__device__ __align__(128) float g_sim[B_ * HW_];
__device__ __align__(128) float g_attn[B_ * HW_];
__device__ __align__(128) float g_mu[B_ * HW_];
__device__ __align__(128) float g_rs[B_ * HW_];
__device__ __align__(128) unsigned g_barcnt;   // monotonic; never reset (replay-safe)

// ---------------- reduction helpers ----------------
__device__ __forceinline__ float warpSum(float v) {
#pragma unroll
    for (int o = 16; o > 0; o >>= 1) v += __shfl_xor_sync(0xffffffffu, v, o);
    return v;
}
__device__ __forceinline__ float warpMax(float v) {
#pragma unroll
    for (int o = 16; o > 0; o >>= 1) v = fmaxf(v, __shfl_xor_sync(0xffffffffu, v, o));
    return v;
}
__device__ float blockSum(float v, float* sm) {
    int lane = threadIdx.x & 31, w = threadIdx.x >> 5;
    int nw = (blockDim.x + 31) >> 5;
    v = warpSum(v);
    if (lane == 0) sm[w] = v;
    __syncthreads();
    if (w == 0) {
        float x = (lane < nw) ? sm[lane] : 0.f;
        x = warpSum(x);
        if (lane == 0) sm[32] = x;
    }
    __syncthreads();
    float r = sm[32];
    __syncthreads();
    return r;
}
__device__ float blockMax(float v, float* sm) {
    int lane = threadIdx.x & 31, w = threadIdx.x >> 5;
    int nw = (blockDim.x + 31) >> 5;
    v = warpMax(v);
    if (lane == 0) sm[w] = v;
    __syncthreads();
    if (w == 0) {
        float x = (lane < nw) ? sm[lane] : -FLT_MAX_V;
        x = warpMax(x);
        if (lane == 0) sm[32] = x;
    }
    __syncthreads();
    float r = sm[32];
    __syncthreads();
    return r;
}

// Grid barrier for exactly FB co-resident blocks (proven R8).
__device__ __forceinline__ void gridBar() {
    __syncthreads();
    if (threadIdx.x == 0) {
        __threadfence();
        unsigned v = atomicAdd(&g_barcnt, 1u);
        unsigned gen = v / FB;
        while ((*(volatile unsigned*)&g_barcnt) / FB == gen) { }
    }
    __syncthreads();
}

// ---------------- K1 (fused front): q -> lora_q -> w_eff -> constants ----------
__global__ void __launch_bounds__(256) k_front(const float* __restrict__ emb,
                                               const float* __restrict__ qg,
                                               const float* __restrict__ qb,
                                               const float* __restrict__ toqw,
                                               const float* __restrict__ lqw,
                                               const float* __restrict__ lkw,
                                               const float* __restrict__ lng,
                                               const float* __restrict__ lnb) {
    __shared__ __align__(16) float t[TD_];
    __shared__ float sm[33];
    __shared__ float sc[8 * 9];
    int tid = threadIdx.x, lane = tid & 31, w = tid >> 5;

    // ---- Phase A: token LN (redundant per block, L2) + q projection ----
    {
        float s = 0.f, s2 = 0.f;
#pragma unroll
        for (int i = 0; i < 3; i++) { float v = emb[tid + 256 * i]; s += v; s2 += v * v; }
        s = blockSum(s, sm);
        s2 = blockSum(s2, sm);
        float mu = s / (float)TD_;
        float var = s2 / (float)TD_ - mu * mu;
        float r = rsqrtf(var + EPSV);
#pragma unroll
        for (int i = 0; i < 3; i++) {
            int idx = tid + 256 * i;
            t[idx] = (emb[idx] - mu) * r * qg[idx] + qb[idx];
        }
        __syncthreads();
        int c = blockIdx.x * 8 + w;
        const float4* row4 = (const float4*)(toqw + (size_t)c * TD_);
        const float4* t4 = (const float4*)t;
        float acc = 0.f;
#pragma unroll
        for (int j = 0; j < 6; j++) {
            float4 a = row4[lane + 32 * j];
            float4 x = t4[lane + 32 * j];
            acc += a.x * x.x + a.y * x.y + a.z * x.z + a.w * x.w;
        }
        acc = warpSum(acc);
        if (lane == 0) g_q[c] = acc;
    }
    gridBar();

    // ---- Phase B: lora_q (blocks 0..7, warp per d, LN folded) ----
    if (blockIdx.x < 8) {
        float s = 0.f, s2 = 0.f;
#pragma unroll
        for (int i = 0; i < 5; i++) { float v = g_q[tid + 256 * i]; s += v; s2 += v * v; }
        s = blockSum(s, sm);
        s2 = blockSum(s2, sm);
        float mu = s / (float)C_;
        float var = s2 / (float)C_ - mu * mu;
        float r = rsqrtf(var + EPSV);
        int d = blockIdx.x * 8 + w;
        const float4* row4 = (const float4*)(lqw + (size_t)d * C_);
        const float4* q4 = (const float4*)g_q;
        float a = 0.f, sr = 0.f;
#pragma unroll
        for (int j = 0; j < 10; j++) {
            float4 rr = row4[lane + 32 * j];
            float4 qq = q4[lane + 32 * j];
            a += rr.x * qq.x + rr.y * qq.y + rr.z * qq.z + rr.w * qq.w;
            sr += rr.x + rr.y + rr.z + rr.w;
        }
        a = warpSum(a);
        sr = warpSum(sr);
        if (lane == 0) g_lq[d] = (a - mu * sr) * r;
    }
    gridBar();

    // ---- Phase C: w_eff (all blocks, warp per c, lanes over d) ----
    {
        int c = blockIdx.x * 8 + w;
        float lq0 = g_lq[lane], lq1 = g_lq[lane + 32];
        float pv = lq0 * lkw[(size_t)lane * C_ + c]
                 + lq1 * lkw[(size_t)(lane + 32) * C_ + c];
        pv = warpSum(pv);
        if (lane == 0) g_w[c] = pv;
    }
    gridBar();

    // ---- Phase D: constants (block 0 only) ----
    if (blockIdx.x != 0) return;
    {
        float p[9];
#pragma unroll
        for (int j = 0; j < 9; j++) p[j] = 0.f;
#pragma unroll
        for (int cc = 0; cc < 5; cc++) {
            int c = tid + 256 * cc;
            float wv = g_w[c];
            float g = lng[c], b = lnb[c];
            p[0] += g; p[1] += g * g; p[2] += g * b; p[3] += b; p[4] += b * b;
            p[5] += g * wv; p[6] += b * wv; p[7] += wv;
            p[8] += fabsf(g - 1.f) + fabsf(b);
        }
#pragma unroll
        for (int j = 0; j < 9; j++) {
            p[j] = warpSum(p[j]);
            if (lane == 0) sc[w * 9 + j] = p[j];
        }
        __syncthreads();
        if (tid < 9) {
            float r = 0.f;
#pragma unroll
            for (int ww = 0; ww < 8; ww++) r += sc[ww * 9 + tid];
            g_cst[tid] = r;
        }
    }
}

// ---------------- K2: sim per row — skips masked rows ----------------
__global__ void __launch_bounds__(256) k_sim(const float* __restrict__ kin,
                                             const float* __restrict__ lng,
                                             const float* __restrict__ lnb,
                                             const float* __restrict__ mask) {
    int row = blockIdx.x * 8 + (threadIdx.x >> 5);   // b*HW+s
    int lane = threadIdx.x & 31;
    if (mask[row] <= 0.f) return;   // masked -> softmax forces -inf; skip 5KB read
    const float4* z4 = (const float4*)(kin + (size_t)row * C_);
    const float4* w4 = (const float4*)g_w;
    bool triv = (g_cst[8] < 1e-6f);
    float S1 = 0.f, S2 = 0.f, S3 = 0.f, S4 = 0.f, S5 = 0.f, S6 = 0.f, S7 = 0.f;
    if (triv) {
#pragma unroll
        for (int j = 0; j < 10; j++) {
            float4 z = z4[lane + 32 * j];
            float4 w = w4[lane + 32 * j];
            S1 += z.x + z.y + z.z + z.w;
            S2 += z.x * z.x + z.y * z.y + z.z * z.z + z.w * z.w;
            S7 += z.x * w.x + z.y * w.y + z.z * w.z + z.w * w.w;
        }
        S3 = S1; S4 = S1; S5 = S2; S6 = 0.f;
    } else {
        const float4* gg4 = (const float4*)lng;
        const float4* bb4 = (const float4*)lnb;
#pragma unroll
        for (int j = 0; j < 10; j++) {
            float4 z = z4[lane + 32 * j];
            float4 g = gg4[lane + 32 * j];
            float4 b = bb4[lane + 32 * j];
            float4 w = w4[lane + 32 * j];
            float gz0 = z.x * g.x, gz1 = z.y * g.y, gz2 = z.z * g.z, gz3 = z.w * g.w;
            S1 += z.x + z.y + z.z + z.w;
            S2 += z.x * z.x + z.y * z.y + z.z * z.z + z.w * z.w;
            S3 += gz0 + gz1 + gz2 + gz3;
            S4 += g.x * gz0 + g.y * gz1 + g.z * gz2 + g.w * gz3;
            S5 += gz0 * gz0 + gz1 * gz1 + gz2 * gz2 + gz3 * gz3;
            S6 += b.x * gz0 + b.y * gz1 + b.z * gz2 + b.w * gz3;
            S7 += w.x * gz0 + w.y * gz1 + w.z * gz2 + w.w * gz3;
        }
    }
    S1 = warpSum(S1); S2 = warpSum(S2); S3 = warpSum(S3); S4 = warpSum(S4);
    S5 = warpSum(S5); S6 = warpSum(S6); S7 = warpSum(S7);
    if (lane == 0) {
        const float Cf = (float)C_;
        float Sg = g_cst[0], Sg2 = g_cst[1], Sgb = g_cst[2], Sb = g_cst[3];
        float Sb2 = g_cst[4], Sgw = g_cst[5], Sbw = g_cst[6], Sw = g_cst[7];
        float mu = S1 / Cf;
        float var = S2 / Cf - mu * mu;
        float r = rsqrtf(var + EPSV);
        float sk  = r * (S3 - mu * Sg) + Sb;
        float mu2 = sk / Cf;
        float sk2 = r * r * (S5 - 2.f * mu * S4 + mu * mu * Sg2)
                  + 2.f * r * (S6 - mu * Sgb) + Sb2;
        float var2 = sk2 / Cf - mu2 * mu2;
        float r2 = rsqrtf(var2 + EPSV);
        float skw = r * (S7 - mu * Sgw) + Sbw;
        g_sim[row] = LORA_SCALE_V * r2 * (skw - mu2 * Sw);
    }
}

// ---------------- K3: per-s LN stats of x (forked) ----------------
__global__ void __launch_bounds__(256) k_xstats(const float* __restrict__ infeat) {
    int b = blockIdx.x >> 4;
    int s0 = (blockIdx.x & 15) * 64;
    int sl = threadIdx.x & 63;
    int cg = threadIdx.x >> 6;    // 0..3
    const float* base = infeat + (size_t)b * C_ * HW_ + s0 + sl;
    float s = 0.f, s2 = 0.f;
#pragma unroll 16
    for (int c = cg; c < C_; c += 4) {
        float v = base[(size_t)c * HW_];
        s += v; s2 += v * v;
    }
    __shared__ float sh[2][4][64];
    sh[0][cg][sl] = s; sh[1][cg][sl] = s2;
    __syncthreads();
    if (cg == 0) {
        s  = sh[0][0][sl] + sh[0][1][sl] + sh[0][2][sl] + sh[0][3][sl];
        s2 = sh[1][0][sl] + sh[1][1][sl] + sh[1][2][sl] + sh[1][3][sl];
        float mu = s / (float)C_;
        float var = s2 / (float)C_ - mu * mu;
        int idx = b * HW_ + s0 + sl;
        g_mu[idx] = mu;
        g_rs[idx] = rsqrtf(var + EPSV);
    }
}

// ---------------- K4: softmax -> attn only (overlaps xstats tail) ----------------
__global__ void k_soft(const float* __restrict__ mask) {
    __shared__ float sm[33];
    int b = blockIdx.x, tid = threadIdx.x;
    float loc[4];
    float mx = -FLT_MAX_V;
#pragma unroll
    for (int i = 0; i < 4; i++) {
        int s = tid + 256 * i;
        float m = mask[b * HW_ + s];
        float sv = (m > 0.f) ? g_sim[b * HW_ + s] : -FLT_MAX_V;
        loc[i] = sv;
        mx = fmaxf(mx, sv);
    }
    mx = blockMax(mx, sm);
    float es = 0.f;
#pragma unroll
    for (int i = 0; i < 4; i++) {
        float e = __expf(loc[i] - mx);
        loc[i] = e; es += e;
    }
    es = blockSum(es, sm);
    float inv = 1.f / es;
#pragma unroll
    for (int i = 0; i < 4; i++) {
        int s = tid + 256 * i;
        g_attn[b * HW_ + s] = loc[i] * inv;
    }
}

// ---------------- K5: light preamble + fg/bg weighted sums (32 c per block) -----
// Preamble: read precomputed attn + mu/rs (12KB L2-hot), build smem wA/wB,
// 2 blockSums for the scalar corrections. Body identical to R13 (4.7 TB/s).
__global__ void __launch_bounds__(256, 3) k_out(const float* __restrict__ infeat,
                                                const float* __restrict__ lng,
                                                const float* __restrict__ lnb,
                                                float* __restrict__ out) {
    __shared__ __align__(16) float wA[HW_];
    __shared__ __align__(16) float wB[HW_];
    __shared__ float sm[33];
    int tid = threadIdx.x, lane = tid & 31, w = tid >> 5;
    int b = blockIdx.x / 40;
    int cg = blockIdx.x - b * 40;      // 0..39, 32 c each

    // ---- light preamble ----
    float pA = 0.f, p2 = 0.f;
    const float invHW = 1.f / (float)HW_;
#pragma unroll
    for (int i = 0; i < 4; i++) {
        int s = tid + 256 * i;
        int idx = b * HW_ + s;
        float attn = g_attn[idx];
        float rs = g_rs[idx], mu = g_mu[idx];
        float a = attn * rs;
        wA[s] = a;
        wB[s] = rs * invHW - a;
        pA += a * mu;
        p2 += mu * rs * invHW;
    }
    float cA = blockSum(pA, sm);
    float cB = blockSum(p2, sm) - cA;

    // ---- body: warp w covers 4 rows c0..c0+3, double-buffered half-rows ----
    int c0 = cg * 32 + w * 4;
    const float4* a4 = (const float4*)wA;
    const float4* w4 = (const float4*)wB;
    const float4* xp = (const float4*)(infeat + (size_t)(b * C_ + c0) * HW_);
    float4 buf0[4], buf1[4];
#pragma unroll
    for (int j = 0; j < 4; j++) buf0[j] = xp[lane + 32 * j];      // row0 first half
    float sfA[4], sbA[4];
#pragma unroll
    for (int r = 0; r < 4; r++) {
        const float4* xr = xp + r * 256;
#pragma unroll
        for (int j = 0; j < 4; j++) buf1[j] = xr[lane + 32 * (j + 4)];  // 2nd half
        float sf = 0.f, sb = 0.f;
#pragma unroll
        for (int j = 0; j < 4; j++) {
            float4 wa = a4[lane + 32 * j];
            float4 wb = w4[lane + 32 * j];
            sf += buf0[j].x * wa.x + buf0[j].y * wa.y + buf0[j].z * wa.z + buf0[j].w * wa.w;
            sb += buf0[j].x * wb.x + buf0[j].y * wb.y + buf0[j].z * wb.z + buf0[j].w * wb.w;
        }
        if (r < 3) {
            const float4* xn = xp + (r + 1) * 256;
#pragma unroll
            for (int j = 0; j < 4; j++) buf0[j] = xn[lane + 32 * j];    // next row 1st half
        }
#pragma unroll
        for (int j = 0; j < 4; j++) {
            float4 wa = a4[lane + 32 * (j + 4)];
            float4 wb = w4[lane + 32 * (j + 4)];
            sf += buf1[j].x * wa.x + buf1[j].y * wa.y + buf1[j].z * wa.z + buf1[j].w * wa.w;
            sb += buf1[j].x * wb.x + buf1[j].y * wb.y + buf1[j].z * wb.z + buf1[j].w * wb.w;
        }
        sfA[r] = sf; sbA[r] = sb;
    }
#pragma unroll
    for (int r = 0; r < 4; r++) {
        float sf = warpSum(sfA[r]);
        float sb = warpSum(sbA[r]);
        if (lane == 0) {
            int c = c0 + r;
            float g = lng[c], bb = lnb[c];
            out[b * (2 * C_) + c]       = g * (sf - cA) + bb;
            out[b * (2 * C_) + C_ + c]  = g * (sb - cB);
        }
    }
}

// ---------------- launch (5 kernels; R13-proven 1-stream/2-event pattern) -------
extern "C" void kernel_launch(void* const* d_in, const int* in_sizes, int n_in,
                              void* d_out, int out_size) {
    const float* layer_infeat  = (const float*)d_in[0];
    const float* layer_inquery = (const float*)d_in[1];
    const float* token_q_emb   = (const float*)d_in[2];
    const float* to_q_w        = (const float*)d_in[3];
    const float* ln_x_g        = (const float*)d_in[4];
    const float* ln_x_b        = (const float*)d_in[5];
    const float* ln_k_g        = (const float*)d_in[6];
    const float* ln_k_b        = (const float*)d_in[7];
    const float* ln_q_g        = (const float*)d_in[8];
    const float* ln_q_b        = (const float*)d_in[9];
    const float* lora_q_w      = (const float*)d_in[10];
    const float* lora_k_w      = (const float*)d_in[11];
    const float* mask          = (const float*)d_in[12];
    float* out = (float*)d_out;

    cudaStream_t s1;
    cudaStreamCreateWithFlags(&s1, cudaStreamNonBlocking);
    cudaEvent_t evF, evB;
    cudaEventCreateWithFlags(&evF, cudaEventDisableTiming);
    cudaEventCreateWithFlags(&evB, cudaEventDisableTiming);

    // Fork: stream B streams ALL of infeat (160MB) while the default stream
    // runs the fused front kernel + the masked inquery pass + softmax.
    cudaEventRecord(evF, 0);
    cudaStreamWaitEvent(s1, evF, 0);
    k_xstats<<<512, 256, 0, s1>>>(layer_infeat);
    cudaEventRecord(evB, s1);

    k_front<<<FB, 256>>>(token_q_emb, ln_q_g, ln_q_b, to_q_w,
                         lora_q_w, lora_k_w, ln_k_g, ln_k_b);
    k_sim<<<4096, 256>>>(layer_inquery, ln_k_g, ln_k_b, mask);
    k_soft<<<32, 256>>>(mask);          // attn only; overlaps xstats tail

    // Join: k_out needs g_attn (default) and g_mu/g_rs (stream B).
    cudaStreamWaitEvent(0, evB, 0);
    k_out<<<B_ * 40, 256>>>(layer_infeat, ln_x_g, ln_x_b, out);
}